// round 1
// baseline (speedup 1.0000x reference)
#include <cuda_runtime.h>

#define BB  16
#define LL  128
#define LRR 128
#define VV  32000

// Scratch (no allocations allowed in kernel_launch)
__device__ float g_probs[BB * LL * LRR];   // [b][j][i]  — probs[b,0,i,j] in ref notation
__device__ int   g_hard[BB * LL];          // argmax per (b,j)
__device__ float g_partial[BB];            // per-batch weighted prob sum
__device__ int   g_is64;                   // labels dtype flag (1 = int64, 0 = int32)

// exp(x) on the FMA pipe: 2^(x*log2e) via magic-number round + degree-4 poly.
// Valid for |x| < ~80; logits are ~N(0,1). Rel err ~3e-5.
__device__ __forceinline__ float fast_exp(float x) {
    float z  = x * 1.4426950408889634f;          // x * log2(e)
    float zf = z + 12582912.0f;                  // round-to-nearest into mantissa (1.5*2^23)
    int   n  = __float_as_int(zf);               // low bits hold round(z) (two's-complement)
    float r  = z - (zf - 12582912.0f);           // r in [-0.5, 0.5]
    float p  = __fmaf_rn(r, 0.0096181291f, 0.0555041086f);
    p        = __fmaf_rn(r, p, 0.2402265069f);
    p        = __fmaf_rn(r, p, 0.6931471806f);
    p        = __fmaf_rn(r, p, 1.0f);
    // scale = 2^n : (n<<23) drops the magic-constant high bits, +127<<23 rebiases
    return p * __int_as_float((n << 23) + 0x3F800000);
}

// Detect labels dtype: int64 little-endian => every odd 32-bit word is the (zero)
// high half. Probability of a false positive with int32 labels in [0,32000):
// (1/32000)^32 ~ 0.
__global__ void kdetect(const int* __restrict__ w) {
    if (threadIdx.x == 0) {
        int all0 = 1;
        #pragma unroll
        for (int k = 0; k < 32; k++) all0 &= (w[2 * k + 1] == 0);
        g_is64 = all0;
    }
}

// One block per (b,j): streaming reduce of 32000 logits -> (sumexp, argmax),
// then gather 128 label probs. Gather hits L1 (row just streamed, 128KB < 228KB L1).
__global__ __launch_bounds__(256) void k1(const float* __restrict__ logits,
                                          const int* __restrict__ lab_raw) {
    const int row = blockIdx.x;          // b*LL + j
    const int b   = row >> 7;
    const int t   = threadIdx.x;
    const float* __restrict__ base = logits + (size_t)row * VV;

    __shared__ float s_s[256];
    __shared__ float s_v[256];
    __shared__ int   s_i[256];
    __shared__ int   s_lab[LRR];
    __shared__ float s_inv;

    if (t < LRR) {
        s_lab[t] = g_is64 ? lab_raw[(b * LRR + t) * 2] : lab_raw[b * LRR + t];
    }

    float acc = 0.0f;
    float vmax = -3.0e38f;
    int   imax = 0;
    const float4* b4 = (const float4*)base;
    #pragma unroll 4
    for (int k = t; k < VV / 4; k += 256) {
        float4 v = __ldg(&b4[k]);
        float e0 = fast_exp(v.x), e1 = fast_exp(v.y);
        float e2 = fast_exp(v.z), e3 = fast_exp(v.w);
        acc += (e0 + e1) + (e2 + e3);
        int i0 = k << 2;
        if (v.x > vmax) { vmax = v.x; imax = i0;     }
        if (v.y > vmax) { vmax = v.y; imax = i0 + 1; }
        if (v.z > vmax) { vmax = v.z; imax = i0 + 2; }
        if (v.w > vmax) { vmax = v.w; imax = i0 + 3; }
    }
    s_s[t] = acc; s_v[t] = vmax; s_i[t] = imax;
    __syncthreads();
    for (int off = 128; off > 0; off >>= 1) {
        if (t < off) {
            s_s[t] += s_s[t + off];
            float v2 = s_v[t + off];
            // first-occurrence argmax (ties -> smaller index), matches jnp.argmax
            if (v2 > s_v[t] || (v2 == s_v[t] && s_i[t + off] < s_i[t])) {
                s_v[t] = v2; s_i[t] = s_i[t + off];
            }
        }
        __syncthreads();
    }
    if (t == 0) {
        s_inv = 1.0f / s_s[0];
        g_hard[row] = s_i[0];
    }
    __syncthreads();
    if (t < LRR) {
        // probs[b,0,i=t,j] = exp(logit[label]) / sumexp ; coalesced store [b][j][i]
        g_probs[row * LRR + t] = fast_exp(__ldg(&base[s_lab[t]])) * s_inv;
    }
}

// One block per batch: sudoku (greedy 1-1 match) + weighted prob sum.
// Final overlap weights: 1.0 selected, 0.5 both-unmatched, 0.1 otherwise:
//   sum = 0.1*S_all + 0.4*S_unmatched_pairs + 0.9*S_selected
__global__ __launch_bounds__(128) void k2(const int* __restrict__ lab_raw) {
    const int b = blockIdx.x;
    const int i = threadIdx.x;

    __shared__ int           s_hard[LL];
    __shared__ int           s_fj[LRR];
    __shared__ unsigned char s_col[LL];
    __shared__ float         s_red[LRR];

    int lab = g_is64 ? lab_raw[(b * LRR + i) * 2] : lab_raw[b * LRR + i];
    s_hard[i] = g_hard[b * LL + i];
    s_col[i]  = 0;
    __syncthreads();

    // row_first: first j with hard[j] == label[i]
    int fj = -1;
    for (int j = 0; j < LL; j++) {
        if (s_hard[j] == lab) { fj = j; break; }
    }
    s_fj[i] = fj;
    __syncthreads();

    // column dedup: keep only the smallest i claiming column fj
    int sel = 0;
    if (fj >= 0) {
        sel = 1;
        for (int ip = 0; ip < i; ip++) {
            if (s_fj[ip] == fj) { sel = 0; break; }
        }
    }
    if (sel) s_col[fj] = 1;   // column j is matched
    __syncthreads();

    const float* pb = g_probs + b * LL * LRR;
    float sum_all = 0.0f, sum_unm = 0.0f;
    for (int j = 0; j < LL; j++) {
        float p = pb[j * LRR + i];           // coalesced across i
        sum_all += p;
        if (!s_col[j]) sum_unm += p;
    }
    float c = 0.1f * sum_all;
    if (sel) c += 0.9f * pb[fj * LRR + i];   // selected cell (row matched)
    else     c += 0.4f * sum_unm;            // row unmatched: both-unmatched cells

    s_red[i] = c;
    __syncthreads();
    for (int off = 64; off > 0; off >>= 1) {
        if (i < off) s_red[i] += s_red[i + off];
        __syncthreads();
    }
    if (i == 0) g_partial[b] = s_red[0];
}

// loss = 1 + mean_b( -2 * total_b / (Lr + L - 1 + 1) ) = 1 - (sum_b total_b) / 2048
__global__ void k3(float* __restrict__ out) {
    if (threadIdx.x == 0) {
        float s = 0.0f;
        #pragma unroll
        for (int b = 0; b < BB; b++) s += g_partial[b];
        out[0] = 1.0f - s * (1.0f / 2048.0f);
    }
}

extern "C" void kernel_launch(void* const* d_in, const int* in_sizes, int n_in,
                              void* d_out, int out_size) {
    // Resolve input order by size (logits: 65.5M elems; labels: 2048)
    int li = (in_sizes[0] > in_sizes[1]) ? 0 : 1;
    const float* logits = (const float*)d_in[li];
    const int*   labels = (const int*)d_in[1 - li];

    kdetect<<<1, 32>>>(labels);
    k1<<<BB * LL, 256>>>(logits, labels);
    k2<<<BB, 128>>>(labels);
    k3<<<1, 32>>>((float*)d_out);
}